// round 3
// baseline (speedup 1.0000x reference)
#include <cuda_runtime.h>
#include <math.h>

#define T_STEPS 400
#define BATCH   256
#define NH      512
#define NCTA    128
#define ROWS    32          // batch rows per CTA tile
#define JC      32          // j-columns per CTA tile (gemm cols = 2*JC: c-half + h-half)
#define AS_STRIDE 520       // 512 + 8 pad (conflict-free row access)
#define SMEM_FLOATS (32*AS_STRIDE + 64*64)

// Persistent state buffers (no cudaMalloc allowed)
__device__ __align__(16) float g_h [BATCH*NH];
__device__ __align__(16) float g_s0[BATCH*NH];
__device__ __align__(16) float g_s1[BATCH*NH];
__device__ __align__(16) float g_s2[BATCH*NH];
__device__ __align__(16) float g_s3[BATCH*NH];
__device__ __align__(16) float g_s5[BATCH*NH];
__device__ unsigned long long g_bar = 0;   // monotonic -> graph-replay safe

__device__ __forceinline__ void grid_barrier() {
    __syncthreads();
    if (threadIdx.x == 0) {
        __threadfence();
        unsigned long long arr    = atomicAdd(&g_bar, 1ULL);
        unsigned long long target = (arr / NCTA + 1ULL) * NCTA;
        while (*(volatile unsigned long long*)&g_bar < target) { __nanosleep(64); }
        __threadfence();
    }
    __syncthreads();
}

// Stage 32 rows x 512 cols of a [256,512] matrix into smem (padded stride)
__device__ __forceinline__ void stage_A(float* As, const float* __restrict__ src,
                                        int row_base, int tid) {
    __syncthreads();   // protect As from readers of previous contents
    #pragma unroll
    for (int i = 0; i < 16; ++i) {
        int idx = tid + i * 256;        // 0..4095 float4s
        int r   = idx >> 7;             // /128
        int c4  = (idx & 127) << 2;     // *4
        float4 v = *(const float4*)(src + (size_t)(row_base + r) * NH + c4);
        *(float4*)(As + r * AS_STRIDE + c4) = v;
    }
}

// acc[0..3]: c-half cols gj..gj+3 ; acc[4..7]: h-half cols (512+gj)..(512+gj+3)
// W row-major [K,1024]; streams rows krow_base..krow_base+511.
__device__ __forceinline__ void gemm_tile(float acc[8], const float* __restrict__ W,
                                          int krow_base, int colc,
                                          const float* As, float* Bs,
                                          int row, int jloc, int tid) {
    float4 pre[4];
    #pragma unroll
    for (int q = 0; q < 4; ++q) {       // prefetch chunk 0
        int idx = tid + q * 256;        // 0..1023
        int k   = idx >> 4;
        int n   = (idx & 15) << 2;
        int col = (n < 32) ? (colc + n) : (512 + colc + n - 32);
        pre[q]  = *(const float4*)(W + (size_t)(krow_base + k) * 1024 + col);
    }
    for (int kc = 0; kc < 8; ++kc) {
        __syncthreads();                // previous compute done before Bs overwrite
        #pragma unroll
        for (int q = 0; q < 4; ++q) {
            int idx = tid + q * 256;
            int k   = idx >> 4;
            int n   = (idx & 15) << 2;
            *(float4*)(Bs + k * 64 + n) = pre[q];
        }
        __syncthreads();
        if (kc < 7) {
            int kb = krow_base + (kc + 1) * 64;
            #pragma unroll
            for (int q = 0; q < 4; ++q) {
                int idx = tid + q * 256;
                int k   = idx >> 4;
                int n   = (idx & 15) << 2;
                int col = (n < 32) ? (colc + n) : (512 + colc + n - 32);
                pre[q]  = *(const float4*)(W + (size_t)(kb + k) * 1024 + col);
            }
        }
        const float* arow = As + row * AS_STRIDE + kc * 64;
        #pragma unroll 16
        for (int k = 0; k < 64; ++k) {
            float  a  = arow[k];
            float4 bc = *(const float4*)(Bs + k * 64 + jloc);
            float4 bh = *(const float4*)(Bs + k * 64 + 32 + jloc);
            acc[0] += a * bc.x; acc[1] += a * bc.y; acc[2] += a * bc.z; acc[3] += a * bc.w;
            acc[4] += a * bh.x; acc[5] += a * bh.y; acc[6] += a * bh.z; acc[7] += a * bh.w;
        }
    }
    __syncthreads();
}

__device__ __forceinline__ float sigf(float x) { return 1.0f / (1.0f + expf(-x)); }

// act: 0 tanh, 1 relu, 2 sigmoid, 3 identity
__device__ __forceinline__ void gate_store(const float acc[8], const float* As,
                                           int row, int gj, int act,
                                           float mean[4], bool do_mean,
                                           float* sdst, int grow) {
    float4 sv;
    float* p = (float*)&sv;
    #pragma unroll
    for (int jj = 0; jj < 4; ++jj) {
        float sp = As[row * AS_STRIDE + gj + jj];
        float c  = acc[jj];
        float hh = acc[4 + jj];
        float hv;
        if      (act == 0) hv = tanhf(hh);
        else if (act == 1) hv = fmaxf(hh, 0.0f);
        else if (act == 2) hv = sigf(hh);
        else               hv = hh;
        float s = sp + sigf(c) * (hv - sp);
        if (do_mean) mean[jj] += s;
        p[jj] = s;
    }
    if (sdst) *(float4*)(sdst + (size_t)grow * NH + gj) = sv;
}

__global__ void __launch_bounds__(256, 1)
rnn_kernel(const float* __restrict__ inputs, const float* __restrict__ hidden0,
           const float* __restrict__ W0, const float* __restrict__ Ws,
           float* __restrict__ out) {
    extern __shared__ float smem[];
    float* As = smem;
    float* Bs = smem + 32 * AS_STRIDE;

    int tid  = threadIdx.x;
    int row  = tid >> 3;            // 0..31 : one batch row per thread
    int jloc = (tid & 7) << 2;      // 0..28 : 4 consecutive j-cols per thread
    int rb   = blockIdx.x >> 4;     // 0..7  row block
    int jb   = blockIdx.x & 15;     // 0..15 col block
    int row_base = rb * ROWS;
    int colc = jb * JC;
    int grow = row_base + row;
    int gj   = colc + jloc;

    for (int t = 0; t < T_STEPS; ++t) {
        float mean[4] = {0.f, 0.f, 0.f, 0.f};

        // ---- L0: s0 = highway(concat(x,h) @ W0) ----
        {
            float acc[8] = {0.f,0.f,0.f,0.f,0.f,0.f,0.f,0.f};
            stage_A(As, inputs + (size_t)t * BATCH * NH, row_base, tid);
            gemm_tile(acc, W0, 0, colc, As, Bs, row, jloc, tid);         // x-pass
            const float* hsrc = (t == 0) ? hidden0 : g_h;
            stage_A(As, hsrc, row_base, tid);
            gemm_tile(acc, W0, 512, colc, As, Bs, row, jloc, tid);       // h-pass
            gate_store(acc, As, row, gj, /*tanh*/0, mean, false, g_s0, grow);
        }
        grid_barrier();

        // ---- L1: node1 = gate(s0 @ Ws[0], tanh) ----
        {
            float acc[8] = {0.f,0.f,0.f,0.f,0.f,0.f,0.f,0.f};
            stage_A(As, g_s0, row_base, tid);
            gemm_tile(acc, Ws + (size_t)0 * 512 * 1024, 0, colc, As, Bs, row, jloc, tid);
            gate_store(acc, As, row, gj, 0, mean, true, g_s1, grow);
        }
        grid_barrier();

        // ---- L2: nodes 2,3,4 (pred s1): relu, relu, identity ----
        {
            stage_A(As, g_s1, row_base, tid);
            const int   widx[3] = {1, 2, 3};
            const int   acts[3] = {1, 1, 3};
            float*      dsts[3] = {g_s2, g_s3, (float*)0};
            for (int q = 0; q < 3; ++q) {
                float acc[8] = {0.f,0.f,0.f,0.f,0.f,0.f,0.f,0.f};
                gemm_tile(acc, Ws + (size_t)widx[q] * 512 * 1024, 0, colc, As, Bs, row, jloc, tid);
                gate_store(acc, As, row, gj, acts[q], mean, true, dsts[q], grow);
            }
        }
        grid_barrier();

        // ---- L3: node5 = gate(s2 @ Ws[4], tanh); node7 = gate(s3 @ Ws[6], tanh) ----
        {
            float acc[8] = {0.f,0.f,0.f,0.f,0.f,0.f,0.f,0.f};
            stage_A(As, g_s2, row_base, tid);
            gemm_tile(acc, Ws + (size_t)4 * 512 * 1024, 0, colc, As, Bs, row, jloc, tid);
            gate_store(acc, As, row, gj, 0, mean, true, g_s5, grow);
        }
        {
            float acc[8] = {0.f,0.f,0.f,0.f,0.f,0.f,0.f,0.f};
            stage_A(As, g_s3, row_base, tid);
            gemm_tile(acc, Ws + (size_t)6 * 512 * 1024, 0, colc, As, Bs, row, jloc, tid);
            gate_store(acc, As, row, gj, 0, mean, true, (float*)0, grow);
        }
        grid_barrier();

        // ---- L4: node6 = gate(s5 @ Ws[5], sigmoid); node8 = gate(s5 @ Ws[7], relu) ----
        {
            stage_A(As, g_s5, row_base, tid);
            {
                float acc[8] = {0.f,0.f,0.f,0.f,0.f,0.f,0.f,0.f};
                gemm_tile(acc, Ws + (size_t)5 * 512 * 1024, 0, colc, As, Bs, row, jloc, tid);
                gate_store(acc, As, row, gj, 2, mean, true, (float*)0, grow);
            }
            {
                float acc[8] = {0.f,0.f,0.f,0.f,0.f,0.f,0.f,0.f};
                gemm_tile(acc, Ws + (size_t)7 * 512 * 1024, 0, colc, As, Bs, row, jloc, tid);
                gate_store(acc, As, row, gj, 1, mean, true, (float*)0, grow);
            }
        }

        // ---- finalize: h_new = mean(states 1..8) ----
        {
            float4 hv;
            hv.x = mean[0] * 0.125f;
            hv.y = mean[1] * 0.125f;
            hv.z = mean[2] * 0.125f;
            hv.w = mean[3] * 0.125f;
            *(float4*)(g_h + (size_t)grow * NH + gj) = hv;
            *(float4*)(out + ((size_t)t * BATCH + grow) * NH + gj) = hv;
            if (t == T_STEPS - 1)
                *(float4*)(out + (size_t)T_STEPS * BATCH * NH + (size_t)grow * NH + gj) = hv;
        }
        grid_barrier();   // publish g_h before next step's h-pass
    }
}

extern "C" void kernel_launch(void* const* d_in, const int* in_sizes, int n_in,
                              void* d_out, int out_size) {
    const float* inputs = (const float*)d_in[0];
    const float* hidden = (const float*)d_in[1];
    const float* W0     = (const float*)d_in[2];
    const float* Ws     = (const float*)d_in[3];
    float* out = (float*)d_out;

    size_t smem_bytes = SMEM_FLOATS * sizeof(float);   // 82,944 B -> 1 CTA/SM, 128 <= 148 SMs (co-resident)
    cudaFuncSetAttribute(rnn_kernel, cudaFuncAttributeMaxDynamicSharedMemorySize, (int)smem_bytes);
    rnn_kernel<<<NCTA, 256, smem_bytes>>>(inputs, hidden, W0, Ws, out);
}

// round 4
// speedup vs baseline: 2.0338x; 2.0338x over previous
#include <cuda_runtime.h>
#include <math.h>

#define T_STEPS 400
#define BATCH   256
#define NH      512
#define NCTA    128
#define AS_STR  1041                 // smem A row stride: 8*1041 % 32 == 8 -> rg banks {0,8,16,24}
#define RED_FLOATS (8*2048)          // 8 warp-partials x (32 rows x 64 cols)
#define SMEM_FLOATS (32*AS_STR + RED_FLOATS)

// Persistent state buffers (no cudaMalloc allowed)
__device__ __align__(16) float g_h [BATCH*NH];
__device__ __align__(16) float g_s0[BATCH*NH];
__device__ __align__(16) float g_s1[BATCH*NH];
__device__ __align__(16) float g_s2[BATCH*NH];
__device__ __align__(16) float g_s3[BATCH*NH];
__device__ __align__(16) float g_s5[BATCH*NH];
__device__ unsigned long long g_bar = 0;   // monotonic -> graph-replay safe

// ---- packed fp32x2 helpers (Blackwell dual-FP32 pipe) ----
#define FMA2(acc, a, b) asm("fma.rn.f32x2 %0, %1, %2, %0;" : "+l"(acc) : "l"(a), "l"(b))
__device__ __forceinline__ unsigned long long pack2(float lo, float hi) {
    unsigned long long r;
    asm("mov.b64 %0, {%1, %2};" : "=l"(r) : "r"(__float_as_uint(lo)), "r"(__float_as_uint(hi)));
    return r;
}
__device__ __forceinline__ float2 unpack2(unsigned long long v) {
    unsigned int lo, hi;
    asm("mov.b64 {%0, %1}, %2;" : "=r"(lo), "=r"(hi) : "l"(v));
    return make_float2(__uint_as_float(lo), __uint_as_float(hi));
}

__device__ __forceinline__ void grid_barrier() {
    __syncthreads();
    if (threadIdx.x == 0) {
        __threadfence();
        unsigned long long arr    = atomicAdd(&g_bar, 1ULL);
        unsigned long long target = (arr / NCTA + 1ULL) * NCTA;
        while (*(volatile unsigned long long*)&g_bar < target) { __nanosleep(64); }
        __threadfence();
    }
    __syncthreads();
}

// Stage 32 rows x 512 cols into As cols [col_off, col_off+512). Coalesced float4 reads.
__device__ __forceinline__ void stage_A(float* As, const float* __restrict__ src,
                                        int row_base, int tid, int col_off) {
    __syncthreads();   // As free of previous readers
    #pragma unroll
    for (int i = 0; i < 16; ++i) {
        int idx = tid + i * 256;        // 0..4095 float4s
        int r   = idx >> 7;             // 0..31
        int c4  = (idx & 127) << 2;     // 0..508
        float4 v = *(const float4*)(src + (size_t)(row_base + r) * NH + c4);
        float* d = As + r * AS_STR + col_off + c4;
        d[0] = v.x; d[1] = v.y; d[2] = v.z; d[3] = v.w;
    }
    __syncthreads();
}

// One warp computes its k-slice of the 32x64 output tile; 8x8 regs/thread, f32x2 FMA.
// W row-major [K,1024]; warp w covers k in [w*KCH, (w+1)*KCH). Partials -> red[w].
template<int KCH>
__device__ __forceinline__ void gemm_pass(const float* __restrict__ As, float* red,
                                          const float* __restrict__ W,
                                          int colc, int w, int rg, int cg) {
    __syncthreads();                       // red free of previous readers
    unsigned long long acc[8][4];
    #pragma unroll
    for (int i = 0; i < 8; ++i)
        #pragma unroll
        for (int p = 0; p < 4; ++p) acc[i][p] = 0ULL;

    int n0   = cg << 3;                                   // local col 0..56
    int wcol = (n0 < 32) ? (colc + n0) : (480 + colc + n0); // 512 + colc + (n0-32)
    const float* Wk = W + (size_t)(w * KCH) * 1024 + wcol;
    const float* Ar = As + (rg << 3) * AS_STR + w * KCH;

    #pragma unroll 4
    for (int kk = 0; kk < KCH; ++kk) {
        float4 b0 = *(const float4*)(Wk);
        float4 b1 = *(const float4*)(Wk + 4);
        Wk += 1024;
        unsigned long long b2[4];
        b2[0] = pack2(b0.x, b0.y); b2[1] = pack2(b0.z, b0.w);
        b2[2] = pack2(b1.x, b1.y); b2[3] = pack2(b1.z, b1.w);
        #pragma unroll
        for (int i = 0; i < 8; ++i) {
            float a = Ar[i * AS_STR + kk];               // broadcast to 8 lanes, conflict-free
            unsigned long long a2 = pack2(a, a);
            FMA2(acc[i][0], a2, b2[0]);
            FMA2(acc[i][1], a2, b2[1]);
            FMA2(acc[i][2], a2, b2[2]);
            FMA2(acc[i][3], a2, b2[3]);
        }
    }

    float* base = red + (w << 11) + ((rg << 3) << 6) + n0;
    #pragma unroll
    for (int i = 0; i < 8; ++i) {
        float2 v0 = unpack2(acc[i][0]), v1 = unpack2(acc[i][1]);
        float2 v2 = unpack2(acc[i][2]), v3 = unpack2(acc[i][3]);
        float* dst = base + (i << 6);
        *(float4*)dst       = make_float4(v0.x, v0.y, v1.x, v1.y);
        *(float4*)(dst + 4) = make_float4(v2.x, v2.y, v3.x, v3.y);
    }
    __syncthreads();                       // partials visible before reduce
}

__device__ __forceinline__ float sigf(float x) { return 1.0f / (1.0f + expf(-x)); }

// 8-way reduce over warp partials, gate, optional mean accum + state store.
// act: 0 tanh, 1 relu, 2 sigmoid, 3 identity. sp_off: As col offset of predecessor state.
__device__ __forceinline__ void reduce_gate(const float* As, const float* red,
                                            int row_r, int jg, int colc, int sp_off,
                                            int act, float mean[4], bool do_mean,
                                            float* sdst, int grow) {
    float c[4] = {0.f,0.f,0.f,0.f}, hh[4] = {0.f,0.f,0.f,0.f};
    #pragma unroll
    for (int w = 0; w < 8; ++w) {
        const float* p = red + (w << 11) + (row_r << 6) + jg;
        float4 pc = *(const float4*)p;
        float4 ph = *(const float4*)(p + 32);
        c[0] += pc.x; c[1] += pc.y; c[2] += pc.z; c[3] += pc.w;
        hh[0] += ph.x; hh[1] += ph.y; hh[2] += ph.z; hh[3] += ph.w;
    }
    float4 sv;
    float* pv = (float*)&sv;
    #pragma unroll
    for (int jj = 0; jj < 4; ++jj) {
        float sp = As[row_r * AS_STR + sp_off + colc + jg + jj];
        float hv;
        if      (act == 0) hv = tanhf(hh[jj]);
        else if (act == 1) hv = fmaxf(hh[jj], 0.0f);
        else if (act == 2) hv = sigf(hh[jj]);
        else               hv = hh[jj];
        float s = sp + sigf(c[jj]) * (hv - sp);
        if (do_mean) mean[jj] += s;
        pv[jj] = s;
    }
    if (sdst) *(float4*)(sdst + (size_t)grow * NH + colc + jg) = sv;
}

__global__ void __launch_bounds__(256, 1)
rnn_kernel(const float* __restrict__ inputs, const float* __restrict__ hidden0,
           const float* __restrict__ W0, const float* __restrict__ Ws,
           float* __restrict__ out) {
    extern __shared__ float smem[];
    float* As  = smem;
    float* red = smem + 32 * AS_STR;

    int tid  = threadIdx.x;
    int w    = tid >> 5;            // warp = k-group
    int lane = tid & 31;
    int rg   = lane >> 3;           // row group: rows rg*8..rg*8+7
    int cg   = lane & 7;            // col group: cols cg*8..cg*8+7 (of 64)
    int row_r = tid >> 3;           // gate ownership: 0..31
    int jg    = (tid & 7) << 2;     // gate j-group: 0..28
    int rb   = blockIdx.x >> 4;     // 0..7 row block
    int jb   = blockIdx.x & 15;     // 0..15 col block
    int row_base = rb * 32;
    int colc = jb * 32;
    int grow = row_base + row_r;

    for (int t = 0; t < T_STEPS; ++t) {
        float mean[4] = {0.f, 0.f, 0.f, 0.f};

        // ---- L0: s0 = highway(concat(x,h) @ W0), fused k=1024 ----
        stage_A(As, inputs + (size_t)t * BATCH * NH, row_base, tid, 0);
        stage_A(As, (t == 0) ? hidden0 : g_h, row_base, tid, 512);
        gemm_pass<128>(As, red, W0, colc, w, rg, cg);
        reduce_gate(As, red, row_r, jg, colc, /*sp_off=*/512, 0, mean, false, g_s0, grow);
        grid_barrier();

        // ---- L1: node1 = gate(s0 @ Ws[0], tanh) ----
        stage_A(As, g_s0, row_base, tid, 0);
        gemm_pass<64>(As, red, Ws + (size_t)0 * 512 * 1024, colc, w, rg, cg);
        reduce_gate(As, red, row_r, jg, colc, 0, 0, mean, true, g_s1, grow);
        grid_barrier();

        // ---- L2: nodes 2,3,4 (pred s1): relu, relu, identity ----
        stage_A(As, g_s1, row_base, tid, 0);
        gemm_pass<64>(As, red, Ws + (size_t)1 * 512 * 1024, colc, w, rg, cg);
        reduce_gate(As, red, row_r, jg, colc, 0, 1, mean, true, g_s2, grow);
        gemm_pass<64>(As, red, Ws + (size_t)2 * 512 * 1024, colc, w, rg, cg);
        reduce_gate(As, red, row_r, jg, colc, 0, 1, mean, true, g_s3, grow);
        gemm_pass<64>(As, red, Ws + (size_t)3 * 512 * 1024, colc, w, rg, cg);
        reduce_gate(As, red, row_r, jg, colc, 0, 3, mean, true, (float*)0, grow);
        grid_barrier();

        // ---- L3: node5 = gate(s2 @ Ws[4], tanh); node7 = gate(s3 @ Ws[6], tanh) ----
        stage_A(As, g_s2, row_base, tid, 0);
        gemm_pass<64>(As, red, Ws + (size_t)4 * 512 * 1024, colc, w, rg, cg);
        reduce_gate(As, red, row_r, jg, colc, 0, 0, mean, true, g_s5, grow);
        stage_A(As, g_s3, row_base, tid, 0);
        gemm_pass<64>(As, red, Ws + (size_t)6 * 512 * 1024, colc, w, rg, cg);
        reduce_gate(As, red, row_r, jg, colc, 0, 0, mean, true, (float*)0, grow);
        grid_barrier();

        // ---- L4: node6 = gate(s5 @ Ws[5], sigmoid); node8 = gate(s5 @ Ws[7], relu) ----
        stage_A(As, g_s5, row_base, tid, 0);
        gemm_pass<64>(As, red, Ws + (size_t)5 * 512 * 1024, colc, w, rg, cg);
        reduce_gate(As, red, row_r, jg, colc, 0, 2, mean, true, (float*)0, grow);
        gemm_pass<64>(As, red, Ws + (size_t)7 * 512 * 1024, colc, w, rg, cg);
        reduce_gate(As, red, row_r, jg, colc, 0, 1, mean, true, (float*)0, grow);

        // ---- finalize: h_new = mean(states 1..8) ----
        {
            float4 hv;
            hv.x = mean[0] * 0.125f;
            hv.y = mean[1] * 0.125f;
            hv.z = mean[2] * 0.125f;
            hv.w = mean[3] * 0.125f;
            int gj = colc + jg;
            *(float4*)(g_h + (size_t)grow * NH + gj) = hv;
            *(float4*)(out + ((size_t)t * BATCH + grow) * NH + gj) = hv;
            if (t == T_STEPS - 1)
                *(float4*)(out + (size_t)T_STEPS * BATCH * NH + (size_t)grow * NH + gj) = hv;
        }
        grid_barrier();   // publish g_h before next step's h staging
    }
}

extern "C" void kernel_launch(void* const* d_in, const int* in_sizes, int n_in,
                              void* d_out, int out_size) {
    const float* inputs = (const float*)d_in[0];
    const float* hidden = (const float*)d_in[1];
    const float* W0     = (const float*)d_in[2];
    const float* Ws     = (const float*)d_in[3];
    float* out = (float*)d_out;

    size_t smem_bytes = SMEM_FLOATS * sizeof(float);   // ~198.8 KB -> 1 CTA/SM, 128 CTAs co-resident
    cudaFuncSetAttribute(rnn_kernel, cudaFuncAttributeMaxDynamicSharedMemorySize, (int)smem_bytes);
    rnn_kernel<<<NCTA, 256, smem_bytes>>>(inputs, hidden, W0, Ws, out);
}

// round 5
// speedup vs baseline: 2.6029x; 1.2798x over previous
#include <cuda_runtime.h>
#include <math.h>

#define T_STEPS 400
#define BATCH   256
#define NH      512
#define NCTA    128
#define NTHR    512
#define AS_STR  1044                 // row stride (floats): %4==0 (float4 align); lane rows rg+4i -> banks {0,8,16,24}+d
#define RED_FLOATS (8*2048)          // 8 k-partials x (32 rows x 64 cols)
#define SMEM_FLOATS (32*AS_STR + RED_FLOATS)   // 33408 + 16384 = 49792 floats = 199,168 B

// Persistent state buffers (no cudaMalloc allowed)
__device__ __align__(16) float g_h [BATCH*NH];
__device__ __align__(16) float g_s0[BATCH*NH];
__device__ __align__(16) float g_s1[BATCH*NH];
__device__ __align__(16) float g_s2[BATCH*NH];
__device__ __align__(16) float g_s3[BATCH*NH];
__device__ __align__(16) float g_s5[BATCH*NH];
__device__ unsigned long long g_bar = 0;   // monotonic -> graph-replay safe

// ---- packed fp32x2 helpers (Blackwell dual-FP32 pipe) ----
#define FMA2(acc, a, b) asm("fma.rn.f32x2 %0, %1, %2, %0;" : "+l"(acc) : "l"(a), "l"(b))
__device__ __forceinline__ unsigned long long pack2(float lo, float hi) {
    unsigned long long r;
    asm("mov.b64 %0, {%1, %2};" : "=l"(r) : "r"(__float_as_uint(lo)), "r"(__float_as_uint(hi)));
    return r;
}
__device__ __forceinline__ float2 unpack2(unsigned long long v) {
    unsigned int lo, hi;
    asm("mov.b64 {%0, %1}, %2;" : "=r"(lo), "=r"(hi) : "l"(v));
    return make_float2(__uint_as_float(lo), __uint_as_float(hi));
}

__device__ __forceinline__ void grid_barrier() {
    __syncthreads();
    if (threadIdx.x == 0) {
        __threadfence();
        unsigned long long arr    = atomicAdd(&g_bar, 1ULL);
        unsigned long long target = (arr / NCTA + 1ULL) * NCTA;
        while (*(volatile unsigned long long*)&g_bar < target) { __nanosleep(64); }
        __threadfence();
    }
    __syncthreads();
}

// Stage 32 rows x 512 cols into As cols [col_off, col_off+512). Coalesced float4.
__device__ __forceinline__ void stage_A(float* As, const float* __restrict__ src,
                                        int row_base, int tid, int col_off) {
    __syncthreads();   // As free of previous readers (gemm's leading sync publishes)
    #pragma unroll
    for (int i = 0; i < 8; ++i) {
        int idx = tid + i * NTHR;       // 0..4095 float4s
        int r   = idx >> 7;             // 0..31
        int c4  = (idx & 127) << 2;     // 0..508
        float4 v = *(const float4*)(src + (size_t)(row_base + r) * NH + c4);
        *(float4*)(As + r * AS_STR + col_off + c4) = v;
    }
}

// Warp (kg,ch): k-slice [kg*KCH,(kg+1)*KCH), column half ch (0=c,1=h), all 32 rows.
// Per-thread: rows rg+4i (i<8), cols ch*32 + cgrp*4 .. +4. Partials -> red[kg].
template<int KCH>
__device__ __forceinline__ void gemm_pass(const float* __restrict__ As, float* red,
                                          const float* __restrict__ W,
                                          int colc, int kg, int ch, int rg, int cgrp) {
    __syncthreads();   // prev reduce done reading red; As staged
    unsigned long long acc[8][2];
    #pragma unroll
    for (int i = 0; i < 8; ++i) { acc[i][0] = 0ULL; acc[i][1] = 0ULL; }

    int wcol = ch * 512 + colc + (cgrp << 2);
    const float* Wb = W + (size_t)(kg * KCH) * 1024 + wcol;
    const float* Ab = As + rg * AS_STR + kg * KCH;

    #pragma unroll 2
    for (int k4 = 0; k4 < KCH; k4 += 4) {
        ulonglong2 bq[4];
        #pragma unroll
        for (int q = 0; q < 4; ++q)
            bq[q] = *(const ulonglong2*)(Wb + (size_t)(k4 + q) * 1024);
        #pragma unroll
        for (int g = 0; g < 2; ++g) {
            float4 av[4];
            #pragma unroll
            for (int i = 0; i < 4; ++i)
                av[i] = *(const float4*)(Ab + (g * 4 + i) * 4 * AS_STR + k4);
            #pragma unroll
            for (int q = 0; q < 4; ++q) {
                #pragma unroll
                for (int i = 0; i < 4; ++i) {
                    float a = (q == 0) ? av[i].x : (q == 1) ? av[i].y
                            : (q == 2) ? av[i].z : av[i].w;
                    unsigned long long a2 = pack2(a, a);
                    FMA2(acc[g * 4 + i][0], a2, bq[q].x);
                    FMA2(acc[g * 4 + i][1], a2, bq[q].y);
                }
            }
        }
    }

    float* base = red + (kg << 11) + ch * 32 + (cgrp << 2);
    #pragma unroll
    for (int i = 0; i < 8; ++i) {
        int row = rg + 4 * i;
        float2 lo = unpack2(acc[i][0]);
        float2 hi = unpack2(acc[i][1]);
        *(float4*)(base + (row << 6)) = make_float4(lo.x, lo.y, hi.x, hi.y);
    }
    __syncthreads();   // partials visible to reduce
}

__device__ __forceinline__ float sigf(float x) { return 1.0f / (1.0f + expf(-x)); }

// 8-way reduce over k-partials, gate, optional mean accum + state store.
// Thread owns (row_r, cols j2,j2+1). act: 0 tanh, 1 relu, 2 sigmoid, 3 identity.
__device__ __forceinline__ void reduce_gate(const float* As, const float* red,
                                            int row_r, int j2, int colc, int sp_off,
                                            int act, float mean[2], bool do_mean,
                                            float* sdst, int grow) {
    float c0 = 0.f, c1 = 0.f, h0 = 0.f, h1 = 0.f;
    #pragma unroll
    for (int w = 0; w < 8; ++w) {
        const float* p = red + (w << 11) + (row_r << 6) + j2;
        float2 pc = *(const float2*)p;
        float2 ph = *(const float2*)(p + 32);
        c0 += pc.x; c1 += pc.y; h0 += ph.x; h1 += ph.y;
    }
    float sp0 = As[row_r * AS_STR + sp_off + colc + j2];
    float sp1 = As[row_r * AS_STR + sp_off + colc + j2 + 1];
    float hv0, hv1;
    if      (act == 0) { hv0 = tanhf(h0);        hv1 = tanhf(h1); }
    else if (act == 1) { hv0 = fmaxf(h0, 0.f);   hv1 = fmaxf(h1, 0.f); }
    else if (act == 2) { hv0 = sigf(h0);         hv1 = sigf(h1); }
    else               { hv0 = h0;               hv1 = h1; }
    float s0 = sp0 + sigf(c0) * (hv0 - sp0);
    float s1 = sp1 + sigf(c1) * (hv1 - sp1);
    if (do_mean) { mean[0] += s0; mean[1] += s1; }
    if (sdst) *(float2*)(sdst + (size_t)grow * NH + colc + j2) = make_float2(s0, s1);
}

__global__ void __launch_bounds__(NTHR, 1)
rnn_kernel(const float* __restrict__ inputs, const float* __restrict__ hidden0,
           const float* __restrict__ W0, const float* __restrict__ Ws,
           float* __restrict__ out) {
    extern __shared__ float smem[];
    float* As  = smem;
    float* red = smem + 32 * AS_STR;

    int tid   = threadIdx.x;
    int w16   = tid >> 5;
    int lane  = tid & 31;
    int kg    = w16 >> 1;           // 0..7 k-group
    int ch    = w16 & 1;            // 0=c half, 1=h half
    int rg    = lane >> 3;          // 0..3 : rows rg+4i
    int cgrp  = lane & 7;           // 0..7 : 4 cols
    int row_r = tid >> 4;           // 0..31 gate row
    int j2    = (tid & 15) << 1;    // 0..30 gate col pair
    int rb    = blockIdx.x >> 4;    // 0..7 row block
    int jb    = blockIdx.x & 15;    // 0..15 col block
    int row_base = rb * 32;
    int colc  = jb * 32;
    int grow  = row_base + row_r;

    for (int t = 0; t < T_STEPS; ++t) {
        float mean[2] = {0.f, 0.f};

        // ---- L0: s0 = highway(concat(x,h) @ W0), fused k=1024 ----
        stage_A(As, inputs + (size_t)t * BATCH * NH, row_base, tid, 0);
        stage_A(As, (t == 0) ? hidden0 : g_h, row_base, tid, 512);
        gemm_pass<128>(As, red, W0, colc, kg, ch, rg, cgrp);
        reduce_gate(As, red, row_r, j2, colc, /*sp_off=*/512, 0, mean, false, g_s0, grow);
        grid_barrier();

        // ---- L1: node1 = gate(s0 @ Ws[0], tanh) ----
        stage_A(As, g_s0, row_base, tid, 0);
        gemm_pass<64>(As, red, Ws + (size_t)0 * 512 * 1024, colc, kg, ch, rg, cgrp);
        reduce_gate(As, red, row_r, j2, colc, 0, 0, mean, true, g_s1, grow);
        grid_barrier();

        // ---- L2: nodes 2,3,4 (pred s1): relu, relu, identity ----
        stage_A(As, g_s1, row_base, tid, 0);
        gemm_pass<64>(As, red, Ws + (size_t)1 * 512 * 1024, colc, kg, ch, rg, cgrp);
        reduce_gate(As, red, row_r, j2, colc, 0, 1, mean, true, g_s2, grow);
        gemm_pass<64>(As, red, Ws + (size_t)2 * 512 * 1024, colc, kg, ch, rg, cgrp);
        reduce_gate(As, red, row_r, j2, colc, 0, 1, mean, true, g_s3, grow);
        gemm_pass<64>(As, red, Ws + (size_t)3 * 512 * 1024, colc, kg, ch, rg, cgrp);
        reduce_gate(As, red, row_r, j2, colc, 0, 3, mean, true, (float*)0, grow);
        grid_barrier();

        // ---- L3: node5 = gate(s2 @ Ws[4], tanh); node7 = gate(s3 @ Ws[6], tanh) ----
        stage_A(As, g_s2, row_base, tid, 0);
        gemm_pass<64>(As, red, Ws + (size_t)4 * 512 * 1024, colc, kg, ch, rg, cgrp);
        reduce_gate(As, red, row_r, j2, colc, 0, 0, mean, true, g_s5, grow);
        stage_A(As, g_s3, row_base, tid, 0);
        gemm_pass<64>(As, red, Ws + (size_t)6 * 512 * 1024, colc, kg, ch, rg, cgrp);
        reduce_gate(As, red, row_r, j2, colc, 0, 0, mean, true, (float*)0, grow);
        grid_barrier();

        // ---- L4: node6 = gate(s5 @ Ws[5], sigmoid); node8 = gate(s5 @ Ws[7], relu) ----
        stage_A(As, g_s5, row_base, tid, 0);
        gemm_pass<64>(As, red, Ws + (size_t)5 * 512 * 1024, colc, kg, ch, rg, cgrp);
        reduce_gate(As, red, row_r, j2, colc, 0, 2, mean, true, (float*)0, grow);
        gemm_pass<64>(As, red, Ws + (size_t)7 * 512 * 1024, colc, kg, ch, rg, cgrp);
        reduce_gate(As, red, row_r, j2, colc, 0, 1, mean, true, (float*)0, grow);

        // ---- finalize: h_new = mean(states 1..8) ----
        {
            float2 hv = make_float2(mean[0] * 0.125f, mean[1] * 0.125f);
            int gj = colc + j2;
            *(float2*)(g_h + (size_t)grow * NH + gj) = hv;
            *(float2*)(out + ((size_t)t * BATCH + grow) * NH + gj) = hv;
            if (t == T_STEPS - 1)
                *(float2*)(out + (size_t)T_STEPS * BATCH * NH + (size_t)grow * NH + gj) = hv;
        }
        grid_barrier();   // publish g_h before next step's h staging
    }
}

extern "C" void kernel_launch(void* const* d_in, const int* in_sizes, int n_in,
                              void* d_out, int out_size) {
    const float* inputs = (const float*)d_in[0];
    const float* hidden = (const float*)d_in[1];
    const float* W0     = (const float*)d_in[2];
    const float* Ws     = (const float*)d_in[3];
    float* out = (float*)d_out;

    size_t smem_bytes = SMEM_FLOATS * sizeof(float);   // 199,168 B -> 1 CTA/SM, 128 CTAs co-resident
    cudaFuncSetAttribute(rnn_kernel, cudaFuncAttributeMaxDynamicSharedMemorySize, (int)smem_bytes);
    rnn_kernel<<<NCTA, NTHR, smem_bytes>>>(inputs, hidden, W0, Ws, out);
}

// round 7
// speedup vs baseline: 3.6135x; 1.3882x over previous
#include <cuda_runtime.h>
#include <cuda_bf16.h>
#include <math.h>
#include <stdint.h>

#define T_STEPS 400
#define BATCH   256
#define NH      512
#define NCTA    128
#define NTHR    256

// ---- smem layout (bytes) ----
#define B_HALF  18432                 // one 128x72(bf16) tile image
#define B_TILE  36864                 // hi+lo
#define SM_B0   0                     // 3 rotating B buffers
#define SM_A    110592                // A: 32 rows x 136 bf16 (272B rows), hi+lo
#define A_HALF  8704
#define SM_RED  128000                // 2 x (32 x 68 fp32)
#define SM_TOTAL 145536

// ---- persistent device buffers (no cudaMalloc allowed) ----
__device__ __align__(16) __nv_bfloat16 g_Bhi[640*9216];   // 40 sched-slots x 16 jb x (128x72)
__device__ __align__(16) __nv_bfloat16 g_Blo[640*9216];
__device__ __align__(16) float g_h [BATCH*NH];
__device__ __align__(16) float g_s0[BATCH*NH];
__device__ __align__(16) float g_s1[BATCH*NH];
__device__ __align__(16) float g_s2[BATCH*NH];
__device__ __align__(16) float g_s3[BATCH*NH];
__device__ __align__(16) float g_s5[BATCH*NH];
__device__ unsigned long long g_bar = 0;                  // monotonic -> graph-replay safe

// ---- asm helpers ----
__device__ __forceinline__ uint32_t smem_u32(const void* p) {
    uint32_t a;
    asm("{ .reg .u64 t; cvta.to.shared.u64 t, %1; cvt.u32.u64 %0, t; }" : "=r"(a) : "l"(p));
    return a;
}
#define CPA16(d, s) asm volatile("cp.async.cg.shared.global [%0], [%1], 16;" :: "r"(d), "l"(s))
#define CPCOMMIT()  asm volatile("cp.async.commit_group;" ::: "memory")
#define CPWAIT2()   asm volatile("cp.async.wait_group 2;" ::: "memory")
#define LDM4(r, a) \
    asm volatile("ldmatrix.sync.aligned.m8n8.x4.shared.b16 {%0,%1,%2,%3}, [%4];" \
        : "=r"((r)[0]), "=r"((r)[1]), "=r"((r)[2]), "=r"((r)[3]) : "r"(a))
#define LDM4T(r, a) \
    asm volatile("ldmatrix.sync.aligned.m8n8.x4.trans.shared.b16 {%0,%1,%2,%3}, [%4];" \
        : "=r"((r)[0]), "=r"((r)[1]), "=r"((r)[2]), "=r"((r)[3]) : "r"(a))
#define MMAB(d, a, b0, b1) \
    asm volatile("mma.sync.aligned.m16n8k16.row.col.f32.bf16.bf16.f32 " \
        "{%0,%1,%2,%3},{%4,%5,%6,%7},{%8,%9},{%0,%1,%2,%3};" \
        : "+f"((d)[0]), "+f"((d)[1]), "+f"((d)[2]), "+f"((d)[3]) \
        : "r"((a)[0]), "r"((a)[1]), "r"((a)[2]), "r"((a)[3]), "r"(b0), "r"(b1))

__device__ __forceinline__ void grid_barrier() {
    __syncthreads();
    if (threadIdx.x == 0) {
        __threadfence();
        unsigned long long arr    = atomicAdd(&g_bar, 1ULL);
        unsigned long long target = (arr / NCTA + 1ULL) * NCTA;
        while (*(volatile unsigned long long*)&g_bar < target) { __nanosleep(64); }
        __threadfence();
    }
    __syncthreads();
}

__device__ __forceinline__ float sigf(float x) { return 1.0f / (1.0f + expf(-x)); }

// Prefetch the B tile for flat chunk q into rotating buffer q%3.
__device__ __forceinline__ void issue_tile(int q, int tid, int jb, uint32_t smu) {
    int sp = q % 40, slot = q % 3;
    const char* gh = (const char*)g_Bhi + ((size_t)sp * 16 + jb) * 18432;
    const char* gl = (const char*)g_Blo + ((size_t)sp * 16 + jb) * 18432;
    uint32_t dst = smu + SM_B0 + slot * B_TILE;
    #pragma unroll
    for (int i = 0; i < 9; ++i) {
        int idx = tid + i * NTHR;               // 0..2303
        if (idx < 1152) CPA16(dst + idx * 16, gh + (size_t)idx * 16);
        else            CPA16(dst + B_HALF + (idx - 1152) * 16, gl + (size_t)(idx - 1152) * 16);
    }
    CPCOMMIT();
}

// Stage A chunk: 32 rows x 128 k fp32 -> bf16 hi/lo, padded 272B rows.
__device__ __forceinline__ void stage_A(char* sm, const float* __restrict__ asrc,
                                        int row_base, int koff, int tid) {
    #pragma unroll
    for (int it = 0; it < 4; ++it) {
        int idx = tid + it * NTHR;              // 0..1023
        int r = idx >> 5, k4 = idx & 31;
        float4 v = *(const float4*)(asrc + (size_t)(row_base + r) * NH + koff + k4 * 4);
        __nv_bfloat16 h0 = __float2bfloat16(v.x), h1 = __float2bfloat16(v.y),
                      h2 = __float2bfloat16(v.z), h3 = __float2bfloat16(v.w);
        __nv_bfloat16 l0 = __float2bfloat16(v.x - __bfloat162float(h0));
        __nv_bfloat16 l1 = __float2bfloat16(v.y - __bfloat162float(h1));
        __nv_bfloat16 l2 = __float2bfloat16(v.z - __bfloat162float(h2));
        __nv_bfloat16 l3 = __float2bfloat16(v.w - __bfloat162float(h3));
        uint32_t ph0 = ((uint32_t)__bfloat16_as_ushort(h1) << 16) | __bfloat16_as_ushort(h0);
        uint32_t ph1 = ((uint32_t)__bfloat16_as_ushort(h3) << 16) | __bfloat16_as_ushort(h2);
        uint32_t pl0 = ((uint32_t)__bfloat16_as_ushort(l1) << 16) | __bfloat16_as_ushort(l0);
        uint32_t pl1 = ((uint32_t)__bfloat16_as_ushort(l3) << 16) | __bfloat16_as_ushort(l2);
        char* ab = sm + SM_A + r * 272 + k4 * 8;
        *(uint2*)ab            = make_uint2(ph0, ph1);
        *(uint2*)(ab + A_HALF) = make_uint2(pl0, pl1);
    }
}

// One K=128 chunk of HMMA. Warp (kh, nw): kh half of ksteps, n cols {nw*8 (c), 32+nw*8 (h)}.
__device__ __forceinline__ void mma_chunk(uint32_t smu, int slot, int lane, int kh, int nw,
                                          float acc[2][2][4]) {
    uint32_t Bb = smu + SM_B0 + slot * B_TILE;
    uint32_t Ab = smu + SM_A;
    int l15 = lane & 15, l16 = lane >> 4;
    #pragma unroll
    for (int ksl = 0; ksl < 4; ++ksl) {
        int ks = kh * 4 + ksl;
        uint32_t ah[2][4], al[2][4], bh[4], bl[4];
        uint32_t kb = (uint32_t)(ks * 16 + l16 * 8) * 2;
        #pragma unroll
        for (int mf = 0; mf < 2; ++mf) {
            uint32_t aa = Ab + (uint32_t)(mf * 16 + l15) * 272 + kb;
            LDM4(ah[mf], aa);
            LDM4(al[mf], aa + A_HALF);
        }
        uint32_t ba = Bb + (uint32_t)(ks * 16 + l15) * 144 + (uint32_t)(nw * 32 + l16 * 16);
        LDM4T(bh, ba);
        LDM4T(bl, ba + B_HALF);
        #pragma unroll
        for (int mf = 0; mf < 2; ++mf) {
            MMAB(acc[mf][0], ah[mf], bh[0], bh[1]);
            MMAB(acc[mf][0], ah[mf], bl[0], bl[1]);
            MMAB(acc[mf][0], al[mf], bh[0], bh[1]);
            MMAB(acc[mf][1], ah[mf], bh[2], bh[3]);
            MMAB(acc[mf][1], ah[mf], bl[2], bl[3]);
            MMAB(acc[mf][1], al[mf], bh[2], bh[3]);
        }
    }
}

// One GEMM level: nch K=128 chunks (A source switches at chunk 4 for L0).
__device__ __forceinline__ void run_level(int nch, const float* aA, const float* aB,
                                          char* sm, uint32_t smu, int tid, int lane,
                                          int kh, int nw, int row_base, int jb,
                                          int& n, float acc[2][2][4]) {
    #pragma unroll
    for (int mf = 0; mf < 2; ++mf)
        #pragma unroll
        for (int nf = 0; nf < 2; ++nf)
            #pragma unroll
            for (int e = 0; e < 4; ++e) acc[mf][nf][e] = 0.f;
    for (int c = 0; c < nch; ++c) {
        issue_tile(n + 2, tid, jb, smu);
        CPWAIT2();
        stage_A(sm, (c < 4) ? aA : aB, row_base, (c & 3) * 128, tid);
        __syncthreads();
        mma_chunk(smu, n % 3, lane, kh, nw, acc);
        __syncthreads();
        ++n;
    }
}

// Reduce k-partials via smem, apply highway gate, store state + mean.
// act: 0 tanh, 1 relu, 2 sigmoid, 3 identity.
__device__ __forceinline__ void red_epilogue(char* sm, const float acc[2][2][4],
                                             int lane, int kh, int nw, int tid,
                                             const float* __restrict__ sp_src, float* sdst,
                                             int act, bool do_mean, float mean[4],
                                             int grow, int gcol) {
    float* red = (float*)(sm + SM_RED) + kh * 2176;       // 32 x 68
    int g = lane >> 2, t4 = lane & 3;
    #pragma unroll
    for (int mf = 0; mf < 2; ++mf)
        #pragma unroll
        for (int nf = 0; nf < 2; ++nf) {
            int row = mf * 16 + g, col = nf * 32 + nw * 8 + t4 * 2;
            *(float2*)(red + row * 68 + col)       = make_float2(acc[mf][nf][0], acc[mf][nf][1]);
            *(float2*)(red + (row + 8) * 68 + col) = make_float2(acc[mf][nf][2], acc[mf][nf][3]);
        }
    __syncthreads();
    int er = tid >> 3, ej = (tid & 7) * 4;
    const float* r0 = (const float*)(sm + SM_RED) + er * 68;
    const float* r1 = r0 + 2176;
    float4 ca = *(const float4*)(r0 + ej);
    float4 cb = *(const float4*)(r1 + ej);
    float4 ha = *(const float4*)(r0 + 32 + ej);
    float4 hb = *(const float4*)(r1 + 32 + ej);
    float c[4]  = {ca.x + cb.x, ca.y + cb.y, ca.z + cb.z, ca.w + cb.w};
    float hh[4] = {ha.x + hb.x, ha.y + hb.y, ha.z + hb.z, ha.w + hb.w};
    float4 sp4 = *(const float4*)(sp_src + (size_t)grow * NH + gcol);
    float sp[4] = {sp4.x, sp4.y, sp4.z, sp4.w};
    float o[4];
    #pragma unroll
    for (int e = 0; e < 4; ++e) {
        float hv = (act == 0) ? tanhf(hh[e])
                 : (act == 1) ? fmaxf(hh[e], 0.0f)
                 : (act == 2) ? sigf(hh[e]) : hh[e];
        float s = sp[e] + sigf(c[e]) * (hv - sp[e]);
        o[e] = s;
        if (do_mean) mean[e] += s;
    }
    if (sdst) *(float4*)(sdst + (size_t)grow * NH + gcol) = make_float4(o[0], o[1], o[2], o[3]);
}

// ---- prepass: pack weights to bf16 hi/lo tiles in the exact smem image ----
__global__ void prepack_kernel(const float* __restrict__ W0, const float* __restrict__ Ws) {
    const int lvl_order[8] = {0, 1, 2, 3, 4, 6, 5, 7};
    const int total = 640 * 128 * 8;                       // (tile, krow, 8-col group)
    for (int idx = blockIdx.x * blockDim.x + threadIdx.x; idx < total; idx += gridDim.x * blockDim.x) {
        int g8 = idx & 7;
        int kr = (idx >> 3) & 127;
        int tt = idx >> 10;                                 // 0..639
        int sp = tt >> 4, jb = tt & 15;
        const float* src; int kbase;
        if (sp < 8) { src = W0; kbase = sp * 128; }
        else { int sp2 = sp - 8; src = Ws + (size_t)lvl_order[sp2 >> 2] * 512 * 1024; kbase = (sp2 & 3) * 128; }
        __align__(16) __nv_bfloat16 hb[8], lb[8];
        #pragma unroll
        for (int e = 0; e < 8; ++e) {
            int cidx = g8 * 8 + e;
            int nw2 = cidx >> 4, w16 = cidx & 15;          // permuted: [c0..7 | h0..7] per n-warp
            int gc = (w16 < 8) ? (jb * 32 + nw2 * 8 + w16)
                               : (512 + jb * 32 + nw2 * 8 + (w16 - 8));
            float wv = src[(size_t)(kbase + kr) * 1024 + gc];
            __nv_bfloat16 h = __float2bfloat16(wv);
            hb[e] = h;
            lb[e] = __float2bfloat16(wv - __bfloat162float(h));
        }
        size_t boff = (size_t)tt * 18432 + kr * 144 + g8 * 16;
        *(uint4*)((char*)g_Bhi + boff) = *(const uint4*)hb;
        *(uint4*)((char*)g_Blo + boff) = *(const uint4*)lb;
    }
}

__global__ void __launch_bounds__(NTHR, 1)
rnn_kernel(const float* __restrict__ inputs, const float* __restrict__ hidden0,
           float* __restrict__ out) {
    extern __shared__ char sm[];
    uint32_t smu = smem_u32(sm);
    int tid = threadIdx.x, lane = tid & 31, warp = tid >> 5;
    int kh = warp >> 2, nw = warp & 3;
    int rb = blockIdx.x >> 4, jb = blockIdx.x & 15;
    int row_base = rb * 32, colc = jb * 32;
    int er = tid >> 3, ej = (tid & 7) * 4;
    int grow = row_base + er, gcol = colc + ej;

    int n = 0;
    issue_tile(0, tid, jb, smu);
    issue_tile(1, tid, jb, smu);

    float acc[2][2][4];
    for (int t = 0; t < T_STEPS; ++t) {
        const float* x    = inputs + (size_t)t * BATCH * NH;
        const float* hsrc = t ? g_h : hidden0;
        float mean[4] = {0.f, 0.f, 0.f, 0.f};

        // L0: s0 = highway(concat(x,h) @ W0), K=1024
        run_level(8, x, hsrc, sm, smu, tid, lane, kh, nw, row_base, jb, n, acc);
        red_epilogue(sm, acc, lane, kh, nw, tid, hsrc, g_s0, 0, false, mean, grow, gcol);
        grid_barrier();
        // n1 = gate(s0 @ Ws0, tanh)
        run_level(4, g_s0, g_s0, sm, smu, tid, lane, kh, nw, row_base, jb, n, acc);
        red_epilogue(sm, acc, lane, kh, nw, tid, g_s0, g_s1, 0, true, mean, grow, gcol);
        grid_barrier();
        // n2,n3,n4 (pred s1): relu, relu, identity
        run_level(4, g_s1, g_s1, sm, smu, tid, lane, kh, nw, row_base, jb, n, acc);
        red_epilogue(sm, acc, lane, kh, nw, tid, g_s1, g_s2, 1, true, mean, grow, gcol);
        run_level(4, g_s1, g_s1, sm, smu, tid, lane, kh, nw, row_base, jb, n, acc);
        red_epilogue(sm, acc, lane, kh, nw, tid, g_s1, g_s3, 1, true, mean, grow, gcol);
        run_level(4, g_s1, g_s1, sm, smu, tid, lane, kh, nw, row_base, jb, n, acc);
        red_epilogue(sm, acc, lane, kh, nw, tid, g_s1, (float*)0, 3, true, mean, grow, gcol);
        grid_barrier();
        // n5 = gate(s2 @ Ws4, tanh); n7 = gate(s3 @ Ws6, tanh)
        run_level(4, g_s2, g_s2, sm, smu, tid, lane, kh, nw, row_base, jb, n, acc);
        red_epilogue(sm, acc, lane, kh, nw, tid, g_s2, g_s5, 0, true, mean, grow, gcol);
        run_level(4, g_s3, g_s3, sm, smu, tid, lane, kh, nw, row_base, jb, n, acc);
        red_epilogue(sm, acc, lane, kh, nw, tid, g_s3, (float*)0, 0, true, mean, grow, gcol);
        grid_barrier();
        // n6 = gate(s5 @ Ws5, sigmoid); n8 = gate(s5 @ Ws7, relu)
        run_level(4, g_s5, g_s5, sm, smu, tid, lane, kh, nw, row_base, jb, n, acc);
        red_epilogue(sm, acc, lane, kh, nw, tid, g_s5, (float*)0, 2, true, mean, grow, gcol);
        run_level(4, g_s5, g_s5, sm, smu, tid, lane, kh, nw, row_base, jb, n, acc);
        red_epilogue(sm, acc, lane, kh, nw, tid, g_s5, (float*)0, 1, true, mean, grow, gcol);

        // finalize: h = mean(states 1..8)
        float4 hv = make_float4(mean[0] * 0.125f, mean[1] * 0.125f,
                                mean[2] * 0.125f, mean[3] * 0.125f);
        *(float4*)(g_h + (size_t)grow * NH + gcol) = hv;
        *(float4*)(out + ((size_t)t * BATCH + grow) * NH + gcol) = hv;
        if (t == T_STEPS - 1)
            *(float4*)(out + (size_t)T_STEPS * BATCH * NH + (size_t)grow * NH + gcol) = hv;
        grid_barrier();
    }
}

extern "C" void kernel_launch(void* const* d_in, const int* in_sizes, int n_in,
                              void* d_out, int out_size) {
    const float* inputs = (const float*)d_in[0];
    const float* hidden = (const float*)d_in[1];
    const float* W0     = (const float*)d_in[2];
    const float* Ws     = (const float*)d_in[3];
    float* out = (float*)d_out;

    prepack_kernel<<<512, 256>>>(W0, Ws);
    cudaFuncSetAttribute(rnn_kernel, cudaFuncAttributeMaxDynamicSharedMemorySize, SM_TOTAL);
    rnn_kernel<<<NCTA, NTHR, SM_TOTAL>>>(inputs, hidden, out);
}